// round 3
// baseline (speedup 1.0000x reference)
#include <cuda_runtime.h>

// PairedKidneyCriticModel: sparse GAT critic, N=4096, H=64, L=3, avg-deg ~33.
// R3: register-resident phase-A scoring (4 nbrs/lane), half-warp-split
// float4 phase-B aggregation, packed {p, row-offset} smem entries.

#define NN 4096
#define HH 64
#define LL 3
#define NW (NN/32)          // 128 mask words per node
#define MAXD 128            // degree cap (mean 33, observed max ~65)
#define SLOPE 0.2f
#define EPSV 1e-5f

// ---- scratch (device globals; no allocation allowed) ----
__device__ unsigned g_bits[NN * NW];        // 2 MB transposed adjacency bits
__device__ unsigned short g_nbr[NN * MAXD]; // 1 MB neighbor ids (ascending)
__device__ int g_deg[NN];
__device__ float g_x [NN * HH];             // embedding (residual input)
__device__ float g_h [NN * HH];             // hidden state
__device__ float g_hw[NN * HH];             // h @ W (L2-resident, 1 MB)
__device__ float g_src[NN];
__device__ float g_dst[NN];
__device__ float g_part[512];
__device__ int g_cnt;

__device__ __forceinline__ float leaky(float e) { return e >= 0.f ? e : SLOPE * e; }

// ---- 1. scan adjacency, set transposed bits (idempotent atomics => deterministic) ----
__global__ __launch_bounds__(256) void k_mask(const float* __restrict__ adj) {
    const long total4 = (long)NN * NN / 4;
    for (long idx = (long)blockIdx.x * blockDim.x + threadIdx.x; idx < total4;
         idx += (long)gridDim.x * blockDim.x) {
        float4 v = ((const float4*)adj)[idx];
        long e = idx * 4;
        int j  = (int)(e >> 12);          // source row of adj
        int i0 = (int)(e & (NN - 1));     // dest column
        float vv[4] = {v.x, v.y, v.z, v.w};
        #pragma unroll
        for (int t = 0; t < 4; t++) {
            int i = i0 + t;
            if (vv[t] != 0.0f && i != j)  // diagonal handled as explicit self-loop
                atomicOr(&g_bits[i * NW + (j >> 5)], 1u << (j & 31));
        }
    }
}

// ---- 2. fused prep: blocks [0,512) build neighbor lists; [512,576) embed ----
__global__ __launch_bounds__(256) void k_prep(
        const float* __restrict__ w1, const float* __restrict__ b1,
        const float* __restrict__ w2, const float* __restrict__ b2,
        const int* __restrict__ tsp, const float* __restrict__ arr,
        const float* __restrict__ dep, const float* __restrict__ hard) {
    __shared__ float AB[192];
    if (blockIdx.x < 512) {
        // --- neighbor-list compaction: one warp per node, ascending order ---
        int warp = threadIdx.x >> 5, lane = threadIdx.x & 31;
        int i = blockIdx.x * 8 + warp;
        const unsigned* __restrict__ bm = &g_bits[i * NW];
        unsigned short* __restrict__ nb = &g_nbr[i * MAXD];
        int base = 0;
        #pragma unroll
        for (int r = 0; r < 4; r++) {
            unsigned word = bm[r * 32 + lane];
            int cnt = __popc(word);
            int pre = cnt;
            #pragma unroll
            for (int off = 1; off < 32; off <<= 1) {
                int v = __shfl_up_sync(0xffffffffu, pre, off);
                if (lane >= off) pre += v;
            }
            int total = __shfl_sync(0xffffffffu, pre, 31);
            int o = base + pre - cnt;
            while (word) {
                int b = __ffs(word) - 1; word &= word - 1;
                if (o < MAXD) nb[o] = (unsigned short)(r * 1024 + lane * 32 + b);
                o++;
            }
            base += total;
        }
        if (lane == 0) g_deg[i] = (base < MAXD) ? base : MAXD;
        if (blockIdx.x == 0 && threadIdx.x == 0) g_cnt = 0;
    } else {
        // --- collapsed embedding: A = w1@w2, B = b1@w2 + b2, then per-node ---
        int t = threadIdx.x;
        if (t < 192) {
            int which = t >> 6, c = t & 63;
            float acc = 0.f;
            for (int h = 0; h < HH; h++) {
                float w = w2[h * HH + c];
                float cf = (which == 0) ? w1[h] : (which == 1 ? w1[HH + h] : b1[h]);
                acc += cf * w;
            }
            if (which == 2) acc += b2[c];
            AB[t] = acc;
        }
        __syncthreads();
        int blk = blockIdx.x - 512;   // 0..63, 64 nodes each
        int raw = tsp[0];
        float ts = (raw > -1000000 && raw < 1000000) ? (float)raw : __int_as_float(raw);
        #pragma unroll
        for (int rep = 0; rep < 16; rep++) {
            int idx = rep * 256 + t;
            int il = idx >> 6, c = idx & 63;
            int i = blk * 64 + il;
            float p = (ts - arr[i]) / (dep[i] - arr[i]);
            g_x[i * HH + c] = p * AB[c] + hard[i] * AB[HH + c] + AB[2 * HH + c];
        }
    }
}

// ---- 3. per-layer: hw = h @ W[l]; src = hw@asrc; dst = hw@adst ----
__global__ __launch_bounds__(256) void k_gemm(
        const float* __restrict__ gw, const float* __restrict__ gas,
        const float* __restrict__ gad, int l) {
    __shared__ float Ws[HH * HH];     // 16 KB
    __shared__ float hs[16 * HH];     // 4 KB
    const float* __restrict__ in = (l == 0) ? g_x : g_h;
    const float* __restrict__ W  = gw + l * HH * HH;
    const float* __restrict__ as = gas + l * HH;
    const float* __restrict__ ad = gad + l * HH;
    int tid = threadIdx.x;            // 256
    int rbase = blockIdx.x * 16;      // 256 blocks
    #pragma unroll
    for (int t = 0; t < 16; t++) Ws[t * 256 + tid] = W[t * 256 + tid];
    #pragma unroll
    for (int t = 0; t < 4; t++) hs[t * 256 + tid] = in[rbase * HH + t * 256 + tid];
    __syncthreads();

    int r  = tid >> 4;
    int c4 = (tid & 15) * 4;
    float4 acc = make_float4(0.f, 0.f, 0.f, 0.f);
    #pragma unroll
    for (int k = 0; k < HH; k++) {
        float hv = hs[r * HH + k];
        float4 wv = *(const float4*)&Ws[k * HH + c4];
        acc.x += hv * wv.x; acc.y += hv * wv.y;
        acc.z += hv * wv.z; acc.w += hv * wv.w;
    }
    int row = rbase + r;
    *(float4*)&g_hw[row * HH + c4] = acc;

    float ps = acc.x * as[c4] + acc.y * as[c4 + 1] + acc.z * as[c4 + 2] + acc.w * as[c4 + 3];
    float pd = acc.x * ad[c4] + acc.y * ad[c4 + 1] + acc.z * ad[c4 + 2] + acc.w * ad[c4 + 3];
    #pragma unroll
    for (int off = 8; off; off >>= 1) {
        ps += __shfl_down_sync(0xffffffffu, ps, off, 16);
        pd += __shfl_down_sync(0xffffffffu, pd, off, 16);
    }
    if ((tid & 15) == 0) { g_src[row] = ps; g_dst[row] = pd; }
}

// ---- 4. sparse attention: reg-resident scoring + half-warp float4 aggregation ----
__global__ __launch_bounds__(256) void k_attn(const float* __restrict__ gb, int l) {
    __shared__ float2 spj[8][MAXD];   // 8 KB: {prob, bitcast(row offset)}
    int warp = threadIdx.x >> 5, lane = threadIdx.x & 31;
    int i = blockIdx.x * 8 + warp;    // 512 blocks x 8 warps
    const float* __restrict__ b = gb + l * HH;
    int deg = g_deg[i];
    float di = g_dst[i];
    float e0 = leaky(g_src[i] + di);  // self-loop score

    // --- phase A: 4 neighbors per lane, all in registers ---
    ushort4 nv = ((const ushort4*)&g_nbr[i * MAXD])[lane];
    int k0 = lane * 4;
    int jj[4] = {nv.x, nv.y, nv.z, nv.w};
    float e[4];
    float m = e0;
    #pragma unroll
    for (int t = 0; t < 4; t++) {
        e[t] = -1e30f;
        if (k0 + t < deg) { e[t] = leaky(g_src[jj[t]] + di); }
        m = fmaxf(m, e[t]);
    }
    #pragma unroll
    for (int off = 16; off; off >>= 1) m = fmaxf(m, __shfl_xor_sync(0xffffffffu, m, off));

    float w0 = __expf(e0 - m);
    float s = 0.f;
    #pragma unroll
    for (int t = 0; t < 4; t++) {
        if (k0 + t < deg) {
            float p = __expf(e[t] - m);
            s += p;
            spj[warp][k0 + t] = make_float2(p, __int_as_float(jj[t] * HH));
        }
    }
    #pragma unroll
    for (int off = 16; off; off >>= 1) s += __shfl_xor_sync(0xffffffffu, s, off);
    s += w0;
    __syncwarp();

    // --- phase B: half-warp split over neighbors, float4 per lane ---
    int half = lane >> 4;
    int f4 = (lane & 15) << 2;
    float4 acc = make_float4(0.f, 0.f, 0.f, 0.f);
    if (half == 0) {                  // self-loop contribution once
        float4 hv = *(const float4*)&g_hw[i * HH + f4];
        acc.x = w0 * hv.x; acc.y = w0 * hv.y; acc.z = w0 * hv.z; acc.w = w0 * hv.w;
    }
    #pragma unroll 4
    for (int k = half; k < deg; k += 2) {
        float2 pj = spj[warp][k];
        const float4 hv = *(const float4*)&g_hw[__float_as_int(pj.y) + f4];
        acc.x += pj.x * hv.x; acc.y += pj.x * hv.y;
        acc.z += pj.x * hv.z; acc.w += pj.x * hv.w;
    }
    // combine halves (fixed order => deterministic)
    acc.x += __shfl_xor_sync(0xffffffffu, acc.x, 16);
    acc.y += __shfl_xor_sync(0xffffffffu, acc.y, 16);
    acc.z += __shfl_xor_sync(0xffffffffu, acc.z, 16);
    acc.w += __shfl_xor_sync(0xffffffffu, acc.w, 16);

    if (half == 0) {
        float inv = 1.0f / s;
        float4 o;
        o.x = acc.x * inv + b[f4];
        o.y = acc.y * inv + b[f4 + 1];
        o.z = acc.z * inv + b[f4 + 2];
        o.w = acc.w * inv + b[f4 + 3];
        if (l < LL - 1) {
            o.x = fmaxf(o.x, 0.f); o.y = fmaxf(o.y, 0.f);
            o.z = fmaxf(o.z, 0.f); o.w = fmaxf(o.w, 0.f);
        }
        *(float4*)&g_h[i * HH + f4] = o;
    }
}

// ---- 5. residual + layernorm + value dot + fused global reduce ----
__global__ __launch_bounds__(256) void k_fin(const float* __restrict__ vw,
                                             const float* __restrict__ vb,
                                             float* __restrict__ out) {
    __shared__ float sacc[8];
    __shared__ int islast;
    __shared__ float sm[256];
    int warp = threadIdx.x >> 5, lane = threadIdx.x & 31;
    int i = blockIdx.x * 8 + warp;          // 512 blocks
    float2 xv = *(const float2*)&g_x[i * HH + 2 * lane];
    float2 hv = *(const float2*)&g_h[i * HH + 2 * lane];
    float v0 = xv.x + hv.x, v1 = xv.y + hv.y;

    float smv = v0 + v1;
    #pragma unroll
    for (int off = 16; off; off >>= 1) smv += __shfl_xor_sync(0xffffffffu, smv, off);
    float mu = smv * (1.0f / 64.0f);
    float d0 = v0 - mu, d1 = v1 - mu;
    float vs = d0 * d0 + d1 * d1;
    #pragma unroll
    for (int off = 16; off; off >>= 1) vs += __shfl_xor_sync(0xffffffffu, vs, off);
    float rstd = rsqrtf(vs * (1.0f / 64.0f) + EPSV);
    float yr = d0 * rstd * vw[2 * lane] + d1 * rstd * vw[2 * lane + 1];
    #pragma unroll
    for (int off = 16; off; off >>= 1) yr += __shfl_xor_sync(0xffffffffu, yr, off);
    if (lane == 0) sacc[warp] = yr;
    __syncthreads();

    if (threadIdx.x == 0) {
        float t = 0.f;
        #pragma unroll
        for (int w = 0; w < 8; w++) t += sacc[w];
        g_part[blockIdx.x] = t;
        __threadfence();
        islast = (atomicAdd(&g_cnt, 1) == 511);
    }
    __syncthreads();
    if (islast) {
        __threadfence();
        float v = g_part[threadIdx.x] + g_part[threadIdx.x + 256];
        sm[threadIdx.x] = v;
        __syncthreads();
        #pragma unroll
        for (int off = 128; off; off >>= 1) {
            if (threadIdx.x < off) sm[threadIdx.x] += sm[threadIdx.x + off];
            __syncthreads();
        }
        if (threadIdx.x == 0)
            out[0] = fmaxf(0.0f, sm[0] * (1.0f / NN) + vb[0]);
    }
}

extern "C" void kernel_launch(void* const* d_in, const int* in_sizes, int n_in,
                              void* d_out, int out_size) {
    const float* adj  = (const float*)d_in[0];
    const int*   ts   = (const int*)  d_in[1];
    const float* arr  = (const float*)d_in[2];
    const float* dep  = (const float*)d_in[3];
    const float* hard = (const float*)d_in[4];
    const float* w1 = (const float*)d_in[6];
    const float* b1 = (const float*)d_in[7];
    const float* w2 = (const float*)d_in[8];
    const float* b2 = (const float*)d_in[9];
    const float* gw  = (const float*)d_in[10];
    const float* gas = (const float*)d_in[11];
    const float* gad = (const float*)d_in[12];
    const float* gb  = (const float*)d_in[13];
    const float* vw  = (const float*)d_in[14];
    const float* vb  = (const float*)d_in[15];
    float* out = (float*)d_out;

    void* bits_ptr = nullptr;
    cudaGetSymbolAddress(&bits_ptr, g_bits);
    cudaMemsetAsync(bits_ptr, 0, sizeof(unsigned) * NN * NW, 0);

    k_mask<<<2048, 256>>>(adj);
    k_prep<<<576, 256>>>(w1, b1, w2, b2, ts, arr, dep, hard);
    for (int l = 0; l < LL; l++) {
        k_gemm<<<NN / 16, 256>>>(gw, gas, gad, l);
        k_attn<<<NN / 8, 256>>>(gb, l);
    }
    k_fin<<<NN / 8, 256>>>(vw, vb, out);
}

// round 4
// speedup vs baseline: 1.0250x; 1.0250x over previous
#include <cuda_runtime.h>

// PairedKidneyCriticModel: sparse GAT critic, N=4096, H=64, L=3, avg-deg ~33.
// R3: register-resident phase-A scoring (4 nbrs/lane), half-warp-split
// float4 phase-B aggregation, packed {p, row-offset} smem entries.

#define NN 4096
#define HH 64
#define LL 3
#define NW (NN/32)          // 128 mask words per node
#define MAXD 128            // degree cap (mean 33, observed max ~65)
#define SLOPE 0.2f
#define EPSV 1e-5f

// ---- scratch (device globals; no allocation allowed) ----
__device__ unsigned g_bits[NN * NW];        // 2 MB transposed adjacency bits
__device__ unsigned short g_nbr[NN * MAXD]; // 1 MB neighbor ids (ascending)
__device__ int g_deg[NN];
__device__ float g_x [NN * HH];             // embedding (residual input)
__device__ float g_h [NN * HH];             // hidden state
__device__ float g_hw[NN * HH];             // h @ W (L2-resident, 1 MB)
__device__ float g_src[NN];
__device__ float g_dst[NN];
__device__ float g_part[512];
__device__ int g_cnt;

__device__ __forceinline__ float leaky(float e) { return e >= 0.f ? e : SLOPE * e; }

// ---- 1. scan adjacency, set transposed bits (idempotent atomics => deterministic) ----
__global__ __launch_bounds__(256) void k_mask(const float* __restrict__ adj) {
    const long total4 = (long)NN * NN / 4;
    for (long idx = (long)blockIdx.x * blockDim.x + threadIdx.x; idx < total4;
         idx += (long)gridDim.x * blockDim.x) {
        float4 v = ((const float4*)adj)[idx];
        long e = idx * 4;
        int j  = (int)(e >> 12);          // source row of adj
        int i0 = (int)(e & (NN - 1));     // dest column
        float vv[4] = {v.x, v.y, v.z, v.w};
        #pragma unroll
        for (int t = 0; t < 4; t++) {
            int i = i0 + t;
            if (vv[t] != 0.0f && i != j)  // diagonal handled as explicit self-loop
                atomicOr(&g_bits[i * NW + (j >> 5)], 1u << (j & 31));
        }
    }
}

// ---- 2. fused prep: blocks [0,512) build neighbor lists; [512,576) embed ----
__global__ __launch_bounds__(256) void k_prep(
        const float* __restrict__ w1, const float* __restrict__ b1,
        const float* __restrict__ w2, const float* __restrict__ b2,
        const int* __restrict__ tsp, const float* __restrict__ arr,
        const float* __restrict__ dep, const float* __restrict__ hard) {
    __shared__ float AB[192];
    if (blockIdx.x < 512) {
        // --- neighbor-list compaction: one warp per node, ascending order ---
        int warp = threadIdx.x >> 5, lane = threadIdx.x & 31;
        int i = blockIdx.x * 8 + warp;
        const unsigned* __restrict__ bm = &g_bits[i * NW];
        unsigned short* __restrict__ nb = &g_nbr[i * MAXD];
        int base = 0;
        #pragma unroll
        for (int r = 0; r < 4; r++) {
            unsigned word = bm[r * 32 + lane];
            int cnt = __popc(word);
            int pre = cnt;
            #pragma unroll
            for (int off = 1; off < 32; off <<= 1) {
                int v = __shfl_up_sync(0xffffffffu, pre, off);
                if (lane >= off) pre += v;
            }
            int total = __shfl_sync(0xffffffffu, pre, 31);
            int o = base + pre - cnt;
            while (word) {
                int b = __ffs(word) - 1; word &= word - 1;
                if (o < MAXD) nb[o] = (unsigned short)(r * 1024 + lane * 32 + b);
                o++;
            }
            base += total;
        }
        if (lane == 0) g_deg[i] = (base < MAXD) ? base : MAXD;
        if (blockIdx.x == 0 && threadIdx.x == 0) g_cnt = 0;
    } else {
        // --- collapsed embedding: A = w1@w2, B = b1@w2 + b2, then per-node ---
        int t = threadIdx.x;
        if (t < 192) {
            int which = t >> 6, c = t & 63;
            float acc = 0.f;
            for (int h = 0; h < HH; h++) {
                float w = w2[h * HH + c];
                float cf = (which == 0) ? w1[h] : (which == 1 ? w1[HH + h] : b1[h]);
                acc += cf * w;
            }
            if (which == 2) acc += b2[c];
            AB[t] = acc;
        }
        __syncthreads();
        int blk = blockIdx.x - 512;   // 0..63, 64 nodes each
        int raw = tsp[0];
        float ts = (raw > -1000000 && raw < 1000000) ? (float)raw : __int_as_float(raw);
        #pragma unroll
        for (int rep = 0; rep < 16; rep++) {
            int idx = rep * 256 + t;
            int il = idx >> 6, c = idx & 63;
            int i = blk * 64 + il;
            float p = (ts - arr[i]) / (dep[i] - arr[i]);
            g_x[i * HH + c] = p * AB[c] + hard[i] * AB[HH + c] + AB[2 * HH + c];
        }
    }
}

// ---- 3. per-layer: hw = h @ W[l]; src = hw@asrc; dst = hw@adst ----
__global__ __launch_bounds__(256) void k_gemm(
        const float* __restrict__ gw, const float* __restrict__ gas,
        const float* __restrict__ gad, int l) {
    __shared__ float Ws[HH * HH];     // 16 KB
    __shared__ float hs[16 * HH];     // 4 KB
    const float* __restrict__ in = (l == 0) ? g_x : g_h;
    const float* __restrict__ W  = gw + l * HH * HH;
    const float* __restrict__ as = gas + l * HH;
    const float* __restrict__ ad = gad + l * HH;
    int tid = threadIdx.x;            // 256
    int rbase = blockIdx.x * 16;      // 256 blocks
    #pragma unroll
    for (int t = 0; t < 16; t++) Ws[t * 256 + tid] = W[t * 256 + tid];
    #pragma unroll
    for (int t = 0; t < 4; t++) hs[t * 256 + tid] = in[rbase * HH + t * 256 + tid];
    __syncthreads();

    int r  = tid >> 4;
    int c4 = (tid & 15) * 4;
    float4 acc = make_float4(0.f, 0.f, 0.f, 0.f);
    #pragma unroll
    for (int k = 0; k < HH; k++) {
        float hv = hs[r * HH + k];
        float4 wv = *(const float4*)&Ws[k * HH + c4];
        acc.x += hv * wv.x; acc.y += hv * wv.y;
        acc.z += hv * wv.z; acc.w += hv * wv.w;
    }
    int row = rbase + r;
    *(float4*)&g_hw[row * HH + c4] = acc;

    float ps = acc.x * as[c4] + acc.y * as[c4 + 1] + acc.z * as[c4 + 2] + acc.w * as[c4 + 3];
    float pd = acc.x * ad[c4] + acc.y * ad[c4 + 1] + acc.z * ad[c4 + 2] + acc.w * ad[c4 + 3];
    #pragma unroll
    for (int off = 8; off; off >>= 1) {
        ps += __shfl_down_sync(0xffffffffu, ps, off, 16);
        pd += __shfl_down_sync(0xffffffffu, pd, off, 16);
    }
    if ((tid & 15) == 0) { g_src[row] = ps; g_dst[row] = pd; }
}

// ---- 4. sparse attention: reg-resident scoring + half-warp float4 aggregation ----
__global__ __launch_bounds__(256) void k_attn(const float* __restrict__ gb, int l) {
    __shared__ float2 spj[8][MAXD];   // 8 KB: {prob, bitcast(row offset)}
    int warp = threadIdx.x >> 5, lane = threadIdx.x & 31;
    int i = blockIdx.x * 8 + warp;    // 512 blocks x 8 warps
    const float* __restrict__ b = gb + l * HH;
    int deg = g_deg[i];
    float di = g_dst[i];
    float e0 = leaky(g_src[i] + di);  // self-loop score

    // --- phase A: 4 neighbors per lane, all in registers ---
    ushort4 nv = ((const ushort4*)&g_nbr[i * MAXD])[lane];
    int k0 = lane * 4;
    int jj[4] = {nv.x, nv.y, nv.z, nv.w};
    float e[4];
    float m = e0;
    #pragma unroll
    for (int t = 0; t < 4; t++) {
        e[t] = -1e30f;
        if (k0 + t < deg) { e[t] = leaky(g_src[jj[t]] + di); }
        m = fmaxf(m, e[t]);
    }
    #pragma unroll
    for (int off = 16; off; off >>= 1) m = fmaxf(m, __shfl_xor_sync(0xffffffffu, m, off));

    float w0 = __expf(e0 - m);
    float s = 0.f;
    #pragma unroll
    for (int t = 0; t < 4; t++) {
        if (k0 + t < deg) {
            float p = __expf(e[t] - m);
            s += p;
            spj[warp][k0 + t] = make_float2(p, __int_as_float(jj[t] * HH));
        }
    }
    #pragma unroll
    for (int off = 16; off; off >>= 1) s += __shfl_xor_sync(0xffffffffu, s, off);
    s += w0;
    __syncwarp();

    // --- phase B: half-warp split over neighbors, float4 per lane ---
    int half = lane >> 4;
    int f4 = (lane & 15) << 2;
    float4 acc = make_float4(0.f, 0.f, 0.f, 0.f);
    if (half == 0) {                  // self-loop contribution once
        float4 hv = *(const float4*)&g_hw[i * HH + f4];
        acc.x = w0 * hv.x; acc.y = w0 * hv.y; acc.z = w0 * hv.z; acc.w = w0 * hv.w;
    }
    #pragma unroll 4
    for (int k = half; k < deg; k += 2) {
        float2 pj = spj[warp][k];
        const float4 hv = *(const float4*)&g_hw[__float_as_int(pj.y) + f4];
        acc.x += pj.x * hv.x; acc.y += pj.x * hv.y;
        acc.z += pj.x * hv.z; acc.w += pj.x * hv.w;
    }
    // combine halves (fixed order => deterministic)
    acc.x += __shfl_xor_sync(0xffffffffu, acc.x, 16);
    acc.y += __shfl_xor_sync(0xffffffffu, acc.y, 16);
    acc.z += __shfl_xor_sync(0xffffffffu, acc.z, 16);
    acc.w += __shfl_xor_sync(0xffffffffu, acc.w, 16);

    if (half == 0) {
        float inv = 1.0f / s;
        float4 o;
        o.x = acc.x * inv + b[f4];
        o.y = acc.y * inv + b[f4 + 1];
        o.z = acc.z * inv + b[f4 + 2];
        o.w = acc.w * inv + b[f4 + 3];
        if (l < LL - 1) {
            o.x = fmaxf(o.x, 0.f); o.y = fmaxf(o.y, 0.f);
            o.z = fmaxf(o.z, 0.f); o.w = fmaxf(o.w, 0.f);
        }
        *(float4*)&g_h[i * HH + f4] = o;
    }
}

// ---- 5. residual + layernorm + value dot + fused global reduce ----
__global__ __launch_bounds__(256) void k_fin(const float* __restrict__ vw,
                                             const float* __restrict__ vb,
                                             float* __restrict__ out) {
    __shared__ float sacc[8];
    __shared__ int islast;
    __shared__ float sm[256];
    int warp = threadIdx.x >> 5, lane = threadIdx.x & 31;
    int i = blockIdx.x * 8 + warp;          // 512 blocks
    float2 xv = *(const float2*)&g_x[i * HH + 2 * lane];
    float2 hv = *(const float2*)&g_h[i * HH + 2 * lane];
    float v0 = xv.x + hv.x, v1 = xv.y + hv.y;

    float smv = v0 + v1;
    #pragma unroll
    for (int off = 16; off; off >>= 1) smv += __shfl_xor_sync(0xffffffffu, smv, off);
    float mu = smv * (1.0f / 64.0f);
    float d0 = v0 - mu, d1 = v1 - mu;
    float vs = d0 * d0 + d1 * d1;
    #pragma unroll
    for (int off = 16; off; off >>= 1) vs += __shfl_xor_sync(0xffffffffu, vs, off);
    float rstd = rsqrtf(vs * (1.0f / 64.0f) + EPSV);
    float yr = d0 * rstd * vw[2 * lane] + d1 * rstd * vw[2 * lane + 1];
    #pragma unroll
    for (int off = 16; off; off >>= 1) yr += __shfl_xor_sync(0xffffffffu, yr, off);
    if (lane == 0) sacc[warp] = yr;
    __syncthreads();

    if (threadIdx.x == 0) {
        float t = 0.f;
        #pragma unroll
        for (int w = 0; w < 8; w++) t += sacc[w];
        g_part[blockIdx.x] = t;
        __threadfence();
        islast = (atomicAdd(&g_cnt, 1) == 511);
    }
    __syncthreads();
    if (islast) {
        __threadfence();
        float v = g_part[threadIdx.x] + g_part[threadIdx.x + 256];
        sm[threadIdx.x] = v;
        __syncthreads();
        #pragma unroll
        for (int off = 128; off; off >>= 1) {
            if (threadIdx.x < off) sm[threadIdx.x] += sm[threadIdx.x + off];
            __syncthreads();
        }
        if (threadIdx.x == 0)
            out[0] = fmaxf(0.0f, sm[0] * (1.0f / NN) + vb[0]);
    }
}

extern "C" void kernel_launch(void* const* d_in, const int* in_sizes, int n_in,
                              void* d_out, int out_size) {
    const float* adj  = (const float*)d_in[0];
    const int*   ts   = (const int*)  d_in[1];
    const float* arr  = (const float*)d_in[2];
    const float* dep  = (const float*)d_in[3];
    const float* hard = (const float*)d_in[4];
    const float* w1 = (const float*)d_in[6];
    const float* b1 = (const float*)d_in[7];
    const float* w2 = (const float*)d_in[8];
    const float* b2 = (const float*)d_in[9];
    const float* gw  = (const float*)d_in[10];
    const float* gas = (const float*)d_in[11];
    const float* gad = (const float*)d_in[12];
    const float* gb  = (const float*)d_in[13];
    const float* vw  = (const float*)d_in[14];
    const float* vb  = (const float*)d_in[15];
    float* out = (float*)d_out;

    void* bits_ptr = nullptr;
    cudaGetSymbolAddress(&bits_ptr, g_bits);
    cudaMemsetAsync(bits_ptr, 0, sizeof(unsigned) * NN * NW, 0);

    k_mask<<<2048, 256>>>(adj);
    k_prep<<<576, 256>>>(w1, b1, w2, b2, ts, arr, dep, hard);
    for (int l = 0; l < LL; l++) {
        k_gemm<<<NN / 16, 256>>>(gw, gas, gad, l);
        k_attn<<<NN / 8, 256>>>(gb, l);
    }
    k_fin<<<NN / 8, 256>>>(vw, vb, out);
}

// round 5
// speedup vs baseline: 1.0343x; 1.0091x over previous
#include <cuda_runtime.h>

// PairedKidneyCriticModel: sparse GAT critic, N=4096, H=64, L=3, avg-deg ~33.
// R4: attention uses 2 warps per node (8192 warps total) — phase B splits
// neighbors over 4 quads (2 warps x 2 half-warps), halving the serial
// L2-latency chain and doubling occupancy.

#define NN 4096
#define HH 64
#define LL 3
#define NW (NN/32)          // 128 mask words per node
#define MAXD 128            // degree cap (mean 33, observed max ~65)
#define SLOPE 0.2f
#define EPSV 1e-5f

// ---- scratch (device globals; no allocation allowed) ----
__device__ unsigned g_bits[NN * NW];        // 2 MB transposed adjacency bits
__device__ unsigned short g_nbr[NN * MAXD]; // 1 MB neighbor ids (ascending)
__device__ int g_deg[NN];
__device__ float g_x [NN * HH];             // embedding (residual input)
__device__ float g_h [NN * HH];             // hidden state
__device__ float g_hw[NN * HH];             // h @ W (L2-resident, 1 MB)
__device__ float g_src[NN];
__device__ float g_dst[NN];
__device__ float g_part[512];
__device__ int g_cnt;

__device__ __forceinline__ float leaky(float e) { return e >= 0.f ? e : SLOPE * e; }

// ---- 1. scan adjacency, set transposed bits (idempotent atomics => deterministic) ----
__global__ __launch_bounds__(256) void k_mask(const float* __restrict__ adj) {
    const long total4 = (long)NN * NN / 4;
    for (long idx = (long)blockIdx.x * blockDim.x + threadIdx.x; idx < total4;
         idx += (long)gridDim.x * blockDim.x) {
        float4 v = ((const float4*)adj)[idx];
        long e = idx * 4;
        int j  = (int)(e >> 12);          // source row of adj
        int i0 = (int)(e & (NN - 1));     // dest column
        float vv[4] = {v.x, v.y, v.z, v.w};
        #pragma unroll
        for (int t = 0; t < 4; t++) {
            int i = i0 + t;
            if (vv[t] != 0.0f && i != j)  // diagonal handled as explicit self-loop
                atomicOr(&g_bits[i * NW + (j >> 5)], 1u << (j & 31));
        }
    }
}

// ---- 2. fused prep: blocks [0,512) build neighbor lists; [512,576) embed ----
__global__ __launch_bounds__(256) void k_prep(
        const float* __restrict__ w1, const float* __restrict__ b1,
        const float* __restrict__ w2, const float* __restrict__ b2,
        const int* __restrict__ tsp, const float* __restrict__ arr,
        const float* __restrict__ dep, const float* __restrict__ hard) {
    __shared__ float AB[192];
    if (blockIdx.x < 512) {
        int warp = threadIdx.x >> 5, lane = threadIdx.x & 31;
        int i = blockIdx.x * 8 + warp;
        const unsigned* __restrict__ bm = &g_bits[i * NW];
        unsigned short* __restrict__ nb = &g_nbr[i * MAXD];
        int base = 0;
        #pragma unroll
        for (int r = 0; r < 4; r++) {
            unsigned word = bm[r * 32 + lane];
            int cnt = __popc(word);
            int pre = cnt;
            #pragma unroll
            for (int off = 1; off < 32; off <<= 1) {
                int v = __shfl_up_sync(0xffffffffu, pre, off);
                if (lane >= off) pre += v;
            }
            int total = __shfl_sync(0xffffffffu, pre, 31);
            int o = base + pre - cnt;
            while (word) {
                int b = __ffs(word) - 1; word &= word - 1;
                if (o < MAXD) nb[o] = (unsigned short)(r * 1024 + lane * 32 + b);
                o++;
            }
            base += total;
        }
        if (lane == 0) g_deg[i] = (base < MAXD) ? base : MAXD;
        if (blockIdx.x == 0 && threadIdx.x == 0) g_cnt = 0;
    } else {
        int t = threadIdx.x;
        if (t < 192) {
            int which = t >> 6, c = t & 63;
            float acc = 0.f;
            for (int h = 0; h < HH; h++) {
                float w = w2[h * HH + c];
                float cf = (which == 0) ? w1[h] : (which == 1 ? w1[HH + h] : b1[h]);
                acc += cf * w;
            }
            if (which == 2) acc += b2[c];
            AB[t] = acc;
        }
        __syncthreads();
        int blk = blockIdx.x - 512;   // 0..63, 64 nodes each
        int raw = tsp[0];
        float ts = (raw > -1000000 && raw < 1000000) ? (float)raw : __int_as_float(raw);
        #pragma unroll
        for (int rep = 0; rep < 16; rep++) {
            int idx = rep * 256 + t;
            int il = idx >> 6, c = idx & 63;
            int i = blk * 64 + il;
            float p = (ts - arr[i]) / (dep[i] - arr[i]);
            g_x[i * HH + c] = p * AB[c] + hard[i] * AB[HH + c] + AB[2 * HH + c];
        }
    }
}

// ---- 3. per-layer: hw = h @ W[l]; src = hw@asrc; dst = hw@adst ----
__global__ __launch_bounds__(256) void k_gemm(
        const float* __restrict__ gw, const float* __restrict__ gas,
        const float* __restrict__ gad, int l) {
    __shared__ float Ws[HH * HH];     // 16 KB
    __shared__ float hs[16 * HH];     // 4 KB
    const float* __restrict__ in = (l == 0) ? g_x : g_h;
    const float* __restrict__ W  = gw + l * HH * HH;
    const float* __restrict__ as = gas + l * HH;
    const float* __restrict__ ad = gad + l * HH;
    int tid = threadIdx.x;            // 256
    int rbase = blockIdx.x * 16;      // 256 blocks
    #pragma unroll
    for (int t = 0; t < 16; t++) Ws[t * 256 + tid] = W[t * 256 + tid];
    #pragma unroll
    for (int t = 0; t < 4; t++) hs[t * 256 + tid] = in[rbase * HH + t * 256 + tid];
    __syncthreads();

    int r  = tid >> 4;
    int c4 = (tid & 15) * 4;
    float4 acc = make_float4(0.f, 0.f, 0.f, 0.f);
    #pragma unroll
    for (int k = 0; k < HH; k++) {
        float hv = hs[r * HH + k];
        float4 wv = *(const float4*)&Ws[k * HH + c4];
        acc.x += hv * wv.x; acc.y += hv * wv.y;
        acc.z += hv * wv.z; acc.w += hv * wv.w;
    }
    int row = rbase + r;
    *(float4*)&g_hw[row * HH + c4] = acc;

    float ps = acc.x * as[c4] + acc.y * as[c4 + 1] + acc.z * as[c4 + 2] + acc.w * as[c4 + 3];
    float pd = acc.x * ad[c4] + acc.y * ad[c4 + 1] + acc.z * ad[c4 + 2] + acc.w * ad[c4 + 3];
    #pragma unroll
    for (int off = 8; off; off >>= 1) {
        ps += __shfl_down_sync(0xffffffffu, ps, off, 16);
        pd += __shfl_down_sync(0xffffffffu, pd, off, 16);
    }
    if ((tid & 15) == 0) { g_src[row] = ps; g_dst[row] = pd; }
}

// ---- 4. sparse attention: 2 warps per node, 4-quad phase-B split ----
__global__ __launch_bounds__(256) void k_attn(const float* __restrict__ gb, int l) {
    __shared__ float2 spj[4][MAXD];     // 4 KB: {prob, bitcast(row offset)}
    __shared__ float2 sw[4];            // {w0, 1/s} per node
    __shared__ float4 accbuf[4][16];    // cross-warp combine, 1 KB
    int warp = threadIdx.x >> 5, lane = threadIdx.x & 31;
    int n    = warp >> 1;               // node slot in block (0..3)
    int sub  = warp & 1;                // warp within pair
    int i = blockIdx.x * 4 + n;         // 1024 blocks x 4 nodes
    const float* __restrict__ b = gb + l * HH;
    int deg = g_deg[i];

    // --- phase A on even warps: 4 neighbors/lane, register-resident ---
    if (sub == 0) {
        float di = g_dst[i];
        float e0 = leaky(g_src[i] + di);            // self-loop score
        ushort4 nv = ((const ushort4*)&g_nbr[i * MAXD])[lane];
        int k0 = lane * 4;
        int jj[4] = {nv.x, nv.y, nv.z, nv.w};
        float e[4];
        float m = e0;
        #pragma unroll
        for (int t = 0; t < 4; t++) {
            e[t] = -1e30f;
            if (k0 + t < deg) e[t] = leaky(g_src[jj[t]] + di);
            m = fmaxf(m, e[t]);
        }
        #pragma unroll
        for (int off = 16; off; off >>= 1)
            m = fmaxf(m, __shfl_xor_sync(0xffffffffu, m, off));
        float w0 = __expf(e0 - m);
        float s = 0.f;
        #pragma unroll
        for (int t = 0; t < 4; t++) {
            if (k0 + t < deg) {
                float p = __expf(e[t] - m);
                s += p;
                spj[n][k0 + t] = make_float2(p, __int_as_float(jj[t] * HH));
            }
        }
        #pragma unroll
        for (int off = 16; off; off >>= 1) s += __shfl_xor_sync(0xffffffffu, s, off);
        s += w0;
        if (lane == 0) sw[n] = make_float2(w0, 1.0f / s);
    }
    __syncthreads();

    // --- phase B: 4 quads (2 warps x 2 half-warps), 4 rows per serial step ---
    int half = lane >> 4;
    int q    = sub * 2 + half;          // quad id 0..3
    int f4   = (lane & 15) << 2;        // feature quad
    float2 ws = sw[n];
    float4 acc = make_float4(0.f, 0.f, 0.f, 0.f);
    if (q == 0) {                       // self-loop contribution once
        float4 hv = *(const float4*)&g_hw[i * HH + f4];
        acc.x = ws.x * hv.x; acc.y = ws.x * hv.y;
        acc.z = ws.x * hv.z; acc.w = ws.x * hv.w;
    }
    #pragma unroll 4
    for (int k = q; k < deg; k += 4) {
        float2 pj = spj[n][k];
        const float4 hv = *(const float4*)&g_hw[__float_as_int(pj.y) + f4];
        acc.x += pj.x * hv.x; acc.y += pj.x * hv.y;
        acc.z += pj.x * hv.z; acc.w += pj.x * hv.w;
    }
    // combine the two half-warps of this warp (fixed order => deterministic)
    acc.x += __shfl_xor_sync(0xffffffffu, acc.x, 16);
    acc.y += __shfl_xor_sync(0xffffffffu, acc.y, 16);
    acc.z += __shfl_xor_sync(0xffffffffu, acc.z, 16);
    acc.w += __shfl_xor_sync(0xffffffffu, acc.w, 16);
    if (sub == 1 && half == 0) accbuf[n][lane] = acc;
    __syncthreads();
    if (sub == 0 && half == 0) {
        float4 o2 = accbuf[n][lane];
        float inv = ws.y;
        float4 o;
        o.x = (acc.x + o2.x) * inv + b[f4];
        o.y = (acc.y + o2.y) * inv + b[f4 + 1];
        o.z = (acc.z + o2.z) * inv + b[f4 + 2];
        o.w = (acc.w + o2.w) * inv + b[f4 + 3];
        if (l < LL - 1) {
            o.x = fmaxf(o.x, 0.f); o.y = fmaxf(o.y, 0.f);
            o.z = fmaxf(o.z, 0.f); o.w = fmaxf(o.w, 0.f);
        }
        *(float4*)&g_h[i * HH + f4] = o;
    }
}

// ---- 5. residual + layernorm + value dot + fused global reduce ----
__global__ __launch_bounds__(256) void k_fin(const float* __restrict__ vw,
                                             const float* __restrict__ vb,
                                             float* __restrict__ out) {
    __shared__ float sacc[8];
    __shared__ int islast;
    __shared__ float sm[256];
    int warp = threadIdx.x >> 5, lane = threadIdx.x & 31;
    int i = blockIdx.x * 8 + warp;          // 512 blocks
    float2 xv = *(const float2*)&g_x[i * HH + 2 * lane];
    float2 hv = *(const float2*)&g_h[i * HH + 2 * lane];
    float v0 = xv.x + hv.x, v1 = xv.y + hv.y;

    float smv = v0 + v1;
    #pragma unroll
    for (int off = 16; off; off >>= 1) smv += __shfl_xor_sync(0xffffffffu, smv, off);
    float mu = smv * (1.0f / 64.0f);
    float d0 = v0 - mu, d1 = v1 - mu;
    float vs = d0 * d0 + d1 * d1;
    #pragma unroll
    for (int off = 16; off; off >>= 1) vs += __shfl_xor_sync(0xffffffffu, vs, off);
    float rstd = rsqrtf(vs * (1.0f / 64.0f) + EPSV);
    float yr = d0 * rstd * vw[2 * lane] + d1 * rstd * vw[2 * lane + 1];
    #pragma unroll
    for (int off = 16; off; off >>= 1) yr += __shfl_xor_sync(0xffffffffu, yr, off);
    if (lane == 0) sacc[warp] = yr;
    __syncthreads();

    if (threadIdx.x == 0) {
        float t = 0.f;
        #pragma unroll
        for (int w = 0; w < 8; w++) t += sacc[w];
        g_part[blockIdx.x] = t;
        __threadfence();
        islast = (atomicAdd(&g_cnt, 1) == 511);
    }
    __syncthreads();
    if (islast) {
        __threadfence();
        float v = g_part[threadIdx.x] + g_part[threadIdx.x + 256];
        sm[threadIdx.x] = v;
        __syncthreads();
        #pragma unroll
        for (int off = 128; off; off >>= 1) {
            if (threadIdx.x < off) sm[threadIdx.x] += sm[threadIdx.x + off];
            __syncthreads();
        }
        if (threadIdx.x == 0)
            out[0] = fmaxf(0.0f, sm[0] * (1.0f / NN) + vb[0]);
    }
}

extern "C" void kernel_launch(void* const* d_in, const int* in_sizes, int n_in,
                              void* d_out, int out_size) {
    const float* adj  = (const float*)d_in[0];
    const int*   ts   = (const int*)  d_in[1];
    const float* arr  = (const float*)d_in[2];
    const float* dep  = (const float*)d_in[3];
    const float* hard = (const float*)d_in[4];
    const float* w1 = (const float*)d_in[6];
    const float* b1 = (const float*)d_in[7];
    const float* w2 = (const float*)d_in[8];
    const float* b2 = (const float*)d_in[9];
    const float* gw  = (const float*)d_in[10];
    const float* gas = (const float*)d_in[11];
    const float* gad = (const float*)d_in[12];
    const float* gb  = (const float*)d_in[13];
    const float* vw  = (const float*)d_in[14];
    const float* vb  = (const float*)d_in[15];
    float* out = (float*)d_out;

    void* bits_ptr = nullptr;
    cudaGetSymbolAddress(&bits_ptr, g_bits);
    cudaMemsetAsync(bits_ptr, 0, sizeof(unsigned) * NN * NW, 0);

    k_mask<<<2048, 256>>>(adj);
    k_prep<<<576, 256>>>(w1, b1, w2, b2, ts, arr, dep, hard);
    for (int l = 0; l < LL; l++) {
        k_gemm<<<NN / 16, 256>>>(gw, gas, gad, l);
        k_attn<<<NN / 4, 256>>>(gb, l);
    }
    k_fin<<<NN / 8, 256>>>(vw, vb, out);
}